// round 5
// baseline (speedup 1.0000x reference)
#include <cuda_runtime.h>

// SheafLoss: B=4 T=1024 P=16 D=64 R=32 K=64, TAU=1
// d_in[0]=m (B,T,P,D) f32, d_in[1]=w (B,T,P) f32,
// d_in[2]=p (B,T,P,K) f32, d_in[3]=patch_centers (R,D) f32
// out: scalar f32

#define BT    4096
#define P_    16
#define D_    64
#define R_    32
#define K_    64
#define TPC   2          // tiles per CTA

__device__ double g_acc;
__device__ float  g_omega[R_ * R_];
__device__ float  g_cn[R_];
__device__ float  g_hs[R_];     // hs[r] = sum_{s != r} omega[r][s]

// ---------------------------------------------------------------------------
// Setup: 4 blocks x 256 threads; block b handles rows [8b, 8b+8).
// omega, cn, hs (omega row-sum minus diagonal), zero accumulator.
// ---------------------------------------------------------------------------
__global__ void __launch_bounds__(256) sheaf_setup_kernel(const float* __restrict__ gc) {
    __shared__ float sc[R_][D_ + 1];
    const int tid = threadIdx.x;
    for (int i = tid; i < R_ * D_; i += 256) sc[i >> 6][i & 63] = gc[i];
    __syncthreads();
    const int r = blockIdx.x * 8 + (tid >> 5);
    const int s = tid & 31;
    float cd = 0.f;
#pragma unroll 8
    for (int d = 0; d < D_; d++) {
        float df = sc[r][d] - sc[s][d];
        cd = fmaf(df, df, cd);
    }
    float omv = expf(-cd);
    g_omega[r * R_ + s] = omv;
    float hs = omv;
#pragma unroll
    for (int off = 16; off; off >>= 1)
        hs += __shfl_xor_sync(0xffffffffu, hs, off);
    if (s == 0) g_hs[r] = hs - 1.0f;           // remove diagonal exp(0)=1
    // cn[r]
    float t = sc[r][s] * sc[r][s] + sc[r][s + 32] * sc[r][s + 32];
#pragma unroll
    for (int off = 16; off; off >>= 1)
        t += __shfl_xor_sync(0xffffffffu, t, off);
    if (s == 1) g_cn[r] = t;
    if (r == 0 && s == 2) g_acc = 0.0;
}

// ---------------------------------------------------------------------------
// Main: one CTA per 2 (b,t) tiles, 256 threads = 8 warps.
// ---------------------------------------------------------------------------
__global__ void __launch_bounds__(256, 5) sheaf_kernel(
    const float* __restrict__ gm,
    const float* __restrict__ gw,
    const float* __restrict__ gp,
    const float* __restrict__ gc)
{
    __shared__ float  s_cT[D_][R_ + 1];   // centers transposed [d][r]
    __shared__ float  s_m[P_ * D_];
    __shared__ float  s_p[P_ * K_];
    __shared__ float  s_sm[P_][R_ + 1];   // start_mass, padded for column reads
    __shared__ float2 s_pb[R_][R_];       // p_bar packed: [r][lane]=(k, k+32)
    __shared__ float  s_w[P_];
    __shared__ float  s_cn[R_];
    __shared__ float  s_hs[R_];
    __shared__ float  s_red[8];

    const int tid  = threadIdx.x;
    const int lane = tid & 31;
    const int wid  = tid >> 5;

    // ---- per-CTA constants ----
    for (int i = tid; i < R_ * D_; i += 256) s_cT[i & 63][i >> 6] = gc[i];
    if (tid < R_) { s_cn[tid] = g_cn[tid]; s_hs[tid] = g_hs[tid]; }

    float lacc = 0.f;   // per-lane:   sum omega * (m*log m) k-slices
    float eacc = 0.f;   // lane-uniform per warp: sum E_r * hs_r over warp's rows

    for (int t = 0; t < TPC; t++) {
        const int bt = blockIdx.x * TPC + t;
        const float* mrow = gm + (size_t)bt * (P_ * D_);
        const float* prow = gp + (size_t)bt * (P_ * K_);
        __syncthreads();   // t=0: covers s_cT; t>0: protects s_m/s_p vs prior pair loop
        ((float4*)s_m)[tid] = ((const float4*)mrow)[tid];
        ((float4*)s_p)[tid] = ((const float4*)prow)[tid];
        if (tid < P_) s_w[tid] = gw[(size_t)bt * P_ + tid];
        __syncthreads();

        // ---- step 1: logits = 2*m.c - |c|^2; 8 warps x 2 patches ----
        {
            const int p0 = wid, p1 = wid + 8;
            const int r = lane;
            float a0 = 0.f, a1 = 0.f;
#pragma unroll
            for (int d = 0; d < D_; d += 4) {
                float c0 = s_cT[d + 0][r];
                float c1 = s_cT[d + 1][r];
                float c2 = s_cT[d + 2][r];
                float c3 = s_cT[d + 3][r];
                float4 mv0 = *(const float4*)&s_m[p0 * D_ + d];
                float4 mv1 = *(const float4*)&s_m[p1 * D_ + d];
                a0 = fmaf(mv0.x, c0, fmaf(mv0.y, c1, fmaf(mv0.z, c2, fmaf(mv0.w, c3, a0))));
                a1 = fmaf(mv1.x, c0, fmaf(mv1.y, c1, fmaf(mv1.z, c2, fmaf(mv1.w, c3, a1))));
            }
            const float cn = s_cn[r];
            float l0 = fmaf(2.f, a0, -cn);
            float l1 = fmaf(2.f, a1, -cn);
            float mx0 = l0, mx1 = l1;
#pragma unroll
            for (int off = 16; off; off >>= 1) {
                mx0 = fmaxf(mx0, __shfl_xor_sync(0xffffffffu, mx0, off));
                mx1 = fmaxf(mx1, __shfl_xor_sync(0xffffffffu, mx1, off));
            }
            float e0 = __expf(l0 - mx0);
            float e1 = __expf(l1 - mx1);
            float sm0 = e0, sm1 = e1;
#pragma unroll
            for (int off = 16; off; off >>= 1) {
                sm0 += __shfl_xor_sync(0xffffffffu, sm0, off);
                sm1 += __shfl_xor_sync(0xffffffffu, sm1, off);
            }
            s_sm[p0][lane] = e0 * (s_w[p0] / sm0);
            s_sm[p1][lane] = e1 * (s_w[p1] / sm1);
        }
        __syncthreads();

        // ---- step 3: total-mass fold + p_bar + E_r (with hs weighting) ----
        {
            float acc[4][2] = {{0.f,0.f},{0.f,0.f},{0.f,0.f},{0.f,0.f}};
#pragma unroll
            for (int pp = 0; pp < P_; pp++) {
                float sp0 = s_p[pp * K_ + lane];
                float sp1 = s_p[pp * K_ + lane + 32];
#pragma unroll
                for (int j = 0; j < 4; j++) {
                    float g = s_sm[pp][wid + 8 * j];
                    acc[j][0] = fmaf(sp0, g, acc[j][0]);
                    acc[j][1] = fmaf(sp1, g, acc[j][1]);
                }
            }
#pragma unroll
            for (int j = 0; j < 4; j++) {
                const int r = wid + 8 * j;
                // total mass of row r: padded column read + 5-shfl reduce
                float v = (lane < P_) ? s_sm[lane][r] : 0.f;
#pragma unroll
                for (int off = 16; off; off >>= 1)
                    v += __shfl_xor_sync(0xffffffffu, v, off);
                float tm = 1.0f / (v + 1e-6f);
                float pb0 = acc[j][0] * tm;
                float pb1 = acc[j][1] * tm;
                s_pb[r][lane] = make_float2(pb0, pb1);
                float e = fmaf(pb0, __logf(pb0 + 1e-8f), pb1 * __logf(pb1 + 1e-8f));
#pragma unroll
                for (int off = 16; off; off >>= 1)
                    e += __shfl_xor_sync(0xffffffffu, e, off);
                eacc = fmaf(e, s_hs[r], eacc);   // lane-uniform
            }
        }
        __syncthreads();

        // ---- pair loop: rows {w, 15-w, 16+w, 31-w} => 62 pairs/warp ----
        {
            const int rows[4] = { wid, 15 - wid, 16 + wid, 31 - wid };
#pragma unroll
            for (int i = 0; i < 4; i++) {
                const int r = rows[i];
                float2 pr = s_pb[r][lane];
                for (int s = r + 1; s < R_; s++) {
                    float2 ps = s_pb[s][lane];
                    float om = __ldg(&g_omega[r * R_ + s]);
                    float m0 = 0.5f * (pr.x + ps.x);
                    float m1 = 0.5f * (pr.y + ps.y);
                    float tt = fmaf(m0, __logf(m0 + 1e-8f), m1 * __logf(m1 + 1e-8f));
                    lacc = fmaf(om, tt, lacc);
                }
            }
        }
    }

    // ---- final reduction (once per CTA) ----
#pragma unroll
    for (int off = 16; off; off >>= 1)
        lacc += __shfl_xor_sync(0xffffffffu, lacc, off);
    if (lane == 0) s_red[wid] = fmaf(0.5f, eacc, -lacc);
    __syncthreads();
    if (tid == 0) {
        float a = 0.f;
#pragma unroll
        for (int i = 0; i < 8; i++) a += s_red[i];
        atomicAdd(&g_acc, (double)a);
    }
}

__global__ void sheaf_finalize_kernel(float* __restrict__ out) {
    out[0] = (float)(g_acc / (496.0 + 1e-8));
}

extern "C" void kernel_launch(void* const* d_in, const int* in_sizes, int n_in,
                              void* d_out, int out_size) {
    const float* m = (const float*)d_in[0];
    const float* w = (const float*)d_in[1];
    const float* p = (const float*)d_in[2];
    const float* c = (const float*)d_in[3];
    float* out = (float*)d_out;
    (void)in_sizes; (void)n_in; (void)out_size;

    sheaf_setup_kernel<<<4, 256>>>(c);
    sheaf_kernel<<<BT / TPC, 256>>>(m, w, p, c);
    sheaf_finalize_kernel<<<1, 1>>>(out);
}

// round 6
// speedup vs baseline: 1.0444x; 1.0444x over previous
#include <cuda_runtime.h>

// SheafLoss: B=4 T=1024 P=16 D=64 R=32 K=64, TAU=1
// d_in[0]=m (B,T,P,D) f32, d_in[1]=w (B,T,P) f32,
// d_in[2]=p (B,T,P,K) f32, d_in[3]=patch_centers (R,D) f32
// out: scalar f32

#define BT    4096
#define P_    16
#define D_    64
#define R_    32
#define K_    64
#define TPC   2          // tiles per CTA
#define LN2   0.6931471805599453f

__device__ double g_acc;
__device__ unsigned int g_done;
__device__ float  g_omega[R_ * R_];
__device__ float  g_cn[R_];
__device__ float  g_hs[R_];     // hs[r] = sum_{s != r} omega[r][s]

// ---------------------------------------------------------------------------
// Setup: 4 blocks x 256 threads; block b handles rows [8b, 8b+8).
// omega, cn, hs; zero accumulator + done-counter (every replay).
// ---------------------------------------------------------------------------
__global__ void __launch_bounds__(256) sheaf_setup_kernel(const float* __restrict__ gc) {
    __shared__ float sc[R_][D_ + 1];
    const int tid = threadIdx.x;
    for (int i = tid; i < R_ * D_; i += 256) sc[i >> 6][i & 63] = gc[i];
    __syncthreads();
    const int r = blockIdx.x * 8 + (tid >> 5);
    const int s = tid & 31;
    float cd = 0.f;
#pragma unroll 8
    for (int d = 0; d < D_; d++) {
        float df = sc[r][d] - sc[s][d];
        cd = fmaf(df, df, cd);
    }
    float omv = expf(-cd);
    g_omega[r * R_ + s] = omv;
    float hs = omv;
#pragma unroll
    for (int off = 16; off; off >>= 1)
        hs += __shfl_xor_sync(0xffffffffu, hs, off);
    if (s == 0) g_hs[r] = hs - 1.0f;           // remove diagonal exp(0)=1
    float t = sc[r][s] * sc[r][s] + sc[r][s + 32] * sc[r][s + 32];
#pragma unroll
    for (int off = 16; off; off >>= 1)
        t += __shfl_xor_sync(0xffffffffu, t, off);
    if (s == 1) g_cn[r] = t;
    if (r == 0 && s == 2) { g_acc = 0.0; g_done = 0u; }
}

// ---------------------------------------------------------------------------
// Main: one CTA per 2 (b,t) tiles, 256 threads = 8 warps.
// Last-finished CTA writes the final scalar (no separate finalize kernel).
// ---------------------------------------------------------------------------
__global__ void __launch_bounds__(256, 5) sheaf_kernel(
    const float* __restrict__ gm,
    const float* __restrict__ gw,
    const float* __restrict__ gp,
    const float* __restrict__ gc,
    float* __restrict__ gout)
{
    __shared__ float  s_c[R_][68];        // centers row-major, 68-pad (16B-aligned rows)
    __shared__ float  s_m[P_ * D_];
    __shared__ float  s_p[P_ * K_];
    __shared__ float  s_sm[P_][R_ + 1];   // start_mass, padded for column reads
    __shared__ float2 s_pb[R_][R_];       // p_bar packed: [r][lane]=(k, k+32)
    __shared__ float  s_w[P_];
    __shared__ float  s_cn[R_];
    __shared__ float  s_hs[R_];
    __shared__ float  s_red[8];

    const int tid  = threadIdx.x;
    const int lane = tid & 31;
    const int wid  = tid >> 5;

    // ---- per-CTA constants ----
    for (int i = tid; i < R_ * D_; i += 256) s_c[i >> 6][i & 63] = gc[i];
    if (tid < R_) { s_cn[tid] = g_cn[tid]; s_hs[tid] = g_hs[tid]; }

    float lacc = 0.f;   // per-lane, log2 domain: sum om * (m*log2 m) k-slices
    float eacc = 0.f;   // lane-uniform per warp: sum E_r * hs_r (natural log)

    for (int t = 0; t < TPC; t++) {
        const int bt = blockIdx.x * TPC + t;
        const float* mrow = gm + (size_t)bt * (P_ * D_);
        const float* prow = gp + (size_t)bt * (P_ * K_);
        __syncthreads();   // t=0: covers s_c; t>0: protects s_m/s_p vs prior pair loop
        ((float4*)s_m)[tid] = ((const float4*)mrow)[tid];
        ((float4*)s_p)[tid] = ((const float4*)prow)[tid];
        if (tid < P_) s_w[tid] = gw[(size_t)bt * P_ + tid];
        __syncthreads();

        // ---- step 1: logits = 2*m.c - |c|^2; 8 warps x 2 patches; lane = r ----
        {
            const int p0 = wid, p1 = wid + 8;
            const int r = lane;
            float a0 = 0.f, a1 = 0.f;
#pragma unroll
            for (int d = 0; d < D_; d += 4) {
                float4 cv  = *(const float4*)&s_c[r][d];          // LDS.128, conflict-free
                float4 mv0 = *(const float4*)&s_m[p0 * D_ + d];   // broadcast
                float4 mv1 = *(const float4*)&s_m[p1 * D_ + d];   // broadcast
                a0 = fmaf(mv0.x, cv.x, fmaf(mv0.y, cv.y, fmaf(mv0.z, cv.z, fmaf(mv0.w, cv.w, a0))));
                a1 = fmaf(mv1.x, cv.x, fmaf(mv1.y, cv.y, fmaf(mv1.z, cv.z, fmaf(mv1.w, cv.w, a1))));
            }
            const float cn = s_cn[r];
            float l0 = fmaf(2.f, a0, -cn);
            float l1 = fmaf(2.f, a1, -cn);
            float mx0 = l0, mx1 = l1;
#pragma unroll
            for (int off = 16; off; off >>= 1) {
                mx0 = fmaxf(mx0, __shfl_xor_sync(0xffffffffu, mx0, off));
                mx1 = fmaxf(mx1, __shfl_xor_sync(0xffffffffu, mx1, off));
            }
            float e0 = __expf(l0 - mx0);
            float e1 = __expf(l1 - mx1);
            float sm0 = e0, sm1 = e1;
#pragma unroll
            for (int off = 16; off; off >>= 1) {
                sm0 += __shfl_xor_sync(0xffffffffu, sm0, off);
                sm1 += __shfl_xor_sync(0xffffffffu, sm1, off);
            }
            s_sm[p0][lane] = e0 * (s_w[p0] / sm0);
            s_sm[p1][lane] = e1 * (s_w[p1] / sm1);
        }
        __syncthreads();

        // ---- step 3: total-mass fold + p_bar + E_r (hs-weighted) ----
        {
            float acc[4][2] = {{0.f,0.f},{0.f,0.f},{0.f,0.f},{0.f,0.f}};
#pragma unroll
            for (int pp = 0; pp < P_; pp++) {
                float sp0 = s_p[pp * K_ + lane];
                float sp1 = s_p[pp * K_ + lane + 32];
#pragma unroll
                for (int j = 0; j < 4; j++) {
                    float g = s_sm[pp][wid + 8 * j];
                    acc[j][0] = fmaf(sp0, g, acc[j][0]);
                    acc[j][1] = fmaf(sp1, g, acc[j][1]);
                }
            }
#pragma unroll
            for (int j = 0; j < 4; j++) {
                const int r = wid + 8 * j;
                float v = (lane < P_) ? s_sm[lane][r] : 0.f;
#pragma unroll
                for (int off = 16; off; off >>= 1)
                    v += __shfl_xor_sync(0xffffffffu, v, off);
                float tm = 1.0f / (v + 1e-6f);
                float pb0 = acc[j][0] * tm;
                float pb1 = acc[j][1] * tm;
                s_pb[r][lane] = make_float2(pb0, pb1);
                float e = fmaf(pb0, __logf(pb0 + 1e-8f), pb1 * __logf(pb1 + 1e-8f));
#pragma unroll
                for (int off = 16; off; off >>= 1)
                    e += __shfl_xor_sync(0xffffffffu, e, off);
                eacc = fmaf(e, s_hs[r], eacc);   // lane-uniform
            }
        }
        __syncthreads();

        // ---- pair loop: rows {w, 15-w, 16+w, 31-w} => 62 pairs/warp ----
        // log2-domain: lacc scaled by ln2 once at the end.
        {
            const int rows[4] = { wid, 15 - wid, 16 + wid, 31 - wid };
#pragma unroll
            for (int i = 0; i < 4; i++) {
                const int r = rows[i];
                float2 prv = s_pb[r][lane];
                const float pr2x = 0.5f * prv.x;
                const float pr2y = 0.5f * prv.y;
                const float* omrow = &g_omega[r * R_];
#pragma unroll 2
                for (int s = r + 1; s < R_; s++) {
                    float2 ps = s_pb[s][lane];
                    float om = __ldg(&omrow[s]);
                    float m0 = fmaf(0.5f, ps.x, pr2x);
                    float m1 = fmaf(0.5f, ps.y, pr2y);
                    float tt = fmaf(m0, __log2f(m0 + 1e-8f), m1 * __log2f(m1 + 1e-8f));
                    lacc = fmaf(om, tt, lacc);
                }
            }
        }
    }

    // ---- final reduction + last-CTA writeout ----
#pragma unroll
    for (int off = 16; off; off >>= 1)
        lacc += __shfl_xor_sync(0xffffffffu, lacc, off);
    if (lane == 0) s_red[wid] = fmaf(0.5f, eacc, -(lacc * LN2));
    __syncthreads();
    if (tid == 0) {
        float a = 0.f;
#pragma unroll
        for (int i = 0; i < 8; i++) a += s_red[i];
        atomicAdd(&g_acc, (double)a);
        __threadfence();
        unsigned int ticket = atomicAdd(&g_done, 1u);
        if (ticket == gridDim.x - 1) {
            double total = *(volatile double*)&g_acc;
            gout[0] = (float)(total / (496.0 + 1e-8));
        }
    }
}

extern "C" void kernel_launch(void* const* d_in, const int* in_sizes, int n_in,
                              void* d_out, int out_size) {
    const float* m = (const float*)d_in[0];
    const float* w = (const float*)d_in[1];
    const float* p = (const float*)d_in[2];
    const float* c = (const float*)d_in[3];
    float* out = (float*)d_out;
    (void)in_sizes; (void)n_in; (void)out_size;

    sheaf_setup_kernel<<<4, 256>>>(c);
    sheaf_kernel<<<BT / TPC, 256>>>(m, w, p, c, out);
}